// round 12
// baseline (speedup 1.0000x reference)
#include <cuda_runtime.h>

#define N_LEAVES   16384
#define DIM        512
#define DEPTH      14
#define N_PAIRS    (N_LEAVES / 2)          // 8192 leaf pairs, one per warp
#define WPB        4                       // warps per block
#define NBLOCKS    (N_PAIRS / WPB)         // 2048
#define MIN_DIST   1e-7f

__device__ double        g_acc;    // zero-init; reset by last block each run
__device__ unsigned int  g_count;

__device__ __forceinline__ float sq4(float4 d) {
    return d.x * d.x + d.y * d.y + d.z * d.z + d.w * d.w;
}

__global__ void __launch_bounds__(128, 6)
tm_fused_kernel(const float* __restrict__ x,
                const float* __restrict__ deltas,
                const float* __restrict__ heights,
                float* __restrict__ out) {
    __shared__ double sacc[WPB];

    const int lane = threadIdx.x & 31;
    const int warp = threadIdx.x >> 5;
    const int pi   = blockIdx.x * WPB + warp;  // leaf-pair index, 0..8191
    const int i0   = pi * 2;                   // even leaf of the pair

    // Warp-owned full row: lane covers float4 chunks {lane, lane+32, lane+64, lane+96}.
    float4 w0 = make_float4(0.f,0.f,0.f,0.f), w1 = w0, w2 = w0, w3 = w0;
    float facc = 0.f;                          // per-lane sq/branch partial

    // ── Path walk, levels 0..13: w += delta; sq term iff this warp owns the node.
    // Node at level l is owned by the unique pair with (pi & mask)==0 (warp-uniform).
    #pragma unroll
    for (int l = 0; l <= 13; l++) {
        const int node = (i0 >> (DEPTH - l)) + ((1 << l) - 1);
        const float4* row = (const float4*)(deltas + (size_t)node * DIM);
        float4 d0 = row[lane], d1 = row[lane + 32], d2 = row[lane + 64], d3 = row[lane + 96];
        w0.x += d0.x; w0.y += d0.y; w0.z += d0.z; w0.w += d0.w;
        w1.x += d1.x; w1.y += d1.y; w1.z += d1.z; w1.w += d1.w;
        w2.x += d2.x; w2.y += d2.y; w2.z += d2.z; w2.w += d2.w;
        w3.x += d3.x; w3.y += d3.y; w3.z += d3.z; w3.w += d3.w;
        if ((pi & ((1 << (13 - l)) - 1)) == 0) {
            float s = sq4(d0) + sq4(d1) + sq4(d2) + sq4(d3);  // per-lane partial
            if (l == 0) facc += s;                            // node 0: no division
            else {
                float br = fmaxf(heights[node] - heights[(node - 1) >> 1], MIN_DIST);
                facc += __fdividef(s, br);
            }
        }
    }

    // ── Leaves + x: 16 independent LDG.128s, then dot accumulation.
    const int n_c0 = i0 + (N_LEAVES - 1);
    const int n_c1 = n_c0 + 1;
    const float hb = heights[(n_c0 - 1) >> 1];
    const float ib0 = __fdividef(1.f, fmaxf(heights[n_c0] - hb, MIN_DIST));
    const float ib1 = __fdividef(1.f, fmaxf(heights[n_c1] - hb, MIN_DIST));

    const float4* dr0 = (const float4*)(deltas + (size_t)n_c0 * DIM);
    const float4* dr1 = (const float4*)(deltas + (size_t)n_c1 * DIM);
    const float4* xr0 = (const float4*)(x + (size_t)i0 * DIM);
    const float4* xr1 = (const float4*)(x + (size_t)(i0 + 1) * DIM);

    float4 c00 = dr0[lane], c01 = dr0[lane+32], c02 = dr0[lane+64], c03 = dr0[lane+96];
    float4 c10 = dr1[lane], c11 = dr1[lane+32], c12 = dr1[lane+64], c13 = dr1[lane+96];
    float4 x00 = xr0[lane], x01 = xr0[lane+32], x02 = xr0[lane+64], x03 = xr0[lane+96];
    float4 x10 = xr1[lane], x11 = xr1[lane+32], x12 = xr1[lane+64], x13 = xr1[lane+96];

    facc += (sq4(c00) + sq4(c01) + sq4(c02) + sq4(c03)) * ib0;
    facc += (sq4(c10) + sq4(c11) + sq4(c12) + sq4(c13)) * ib1;

    float dot0 =
        x00.x*(w0.x+c00.x) + x00.y*(w0.y+c00.y) + x00.z*(w0.z+c00.z) + x00.w*(w0.w+c00.w) +
        x01.x*(w1.x+c01.x) + x01.y*(w1.y+c01.y) + x01.z*(w1.z+c01.z) + x01.w*(w1.w+c01.w) +
        x02.x*(w2.x+c02.x) + x02.y*(w2.y+c02.y) + x02.z*(w2.z+c02.z) + x02.w*(w2.w+c02.w) +
        x03.x*(w3.x+c03.x) + x03.y*(w3.y+c03.y) + x03.z*(w3.z+c03.z) + x03.w*(w3.w+c03.w);
    float dot1 =
        x10.x*(w0.x+c10.x) + x10.y*(w0.y+c10.y) + x10.z*(w0.z+c10.z) + x10.w*(w0.w+c10.w) +
        x11.x*(w1.x+c11.x) + x11.y*(w1.y+c11.y) + x11.z*(w1.z+c11.z) + x11.w*(w1.w+c11.w) +
        x12.x*(w2.x+c12.x) + x12.y*(w2.y+c12.y) + x12.z*(w2.z+c12.z) + x12.w*(w2.w+c12.w) +
        x13.x*(w3.x+c13.x) + x13.y*(w3.y+c13.y) + x13.z*(w3.z+c13.z) + x13.w*(w3.w+c13.w);

    // ── In-warp reductions; outputs need no block barrier.
    #pragma unroll
    for (int off = 16; off; off >>= 1) {
        dot0 += __shfl_down_sync(0xffffffffu, dot0, off);
        dot1 += __shfl_down_sync(0xffffffffu, dot1, off);
        facc += __shfl_down_sync(0xffffffffu, facc, off);
    }
    if (lane == 0) {
        out[i0]     = dot0;
        out[i0 + 1] = dot1;
        sacc[warp]  = (double)facc;
    }

    // ── Tiny end-of-block fold + last-block scalar epilogue.
    __syncthreads();
    if (threadIdx.x == 0) {
        atomicAdd(&g_acc, sacc[0] + sacc[1] + sacc[2] + sacc[3]);
        __threadfence();
        unsigned int prev = atomicAdd(&g_count, 1u);
        if (prev == (unsigned int)(gridDim.x - 1)) {
            out[N_LEAVES] = (float)(*(volatile double*)&g_acc);
            g_acc   = 0.0;   // graph-replay safe
            g_count = 0u;
        }
    }
}

extern "C" void kernel_launch(void* const* d_in, const int* in_sizes, int n_in,
                              void* d_out, int out_size) {
    const float* x       = (const float*)d_in[0];
    const float* deltas  = (const float*)d_in[1];
    const float* heights = (const float*)d_in[2];
    float* out = (float*)d_out;

    tm_fused_kernel<<<NBLOCKS, 128>>>(x, deltas, heights, out);
}

// round 13
// speedup vs baseline: 1.3477x; 1.3477x over previous
#include <cuda_runtime.h>

#define N_LEAVES   16384
#define DIM        512
#define DEPTH      14
#define K          4                       // subtree depth per block -> 16 leaves
#define LPB        (1 << K)                // 16 leaves per block
#define NBLOCKS    (N_LEAVES / LPB)        // 1024  (single wave: <= 148*7)
#define ROOT_LEVEL (DEPTH - K)             // 10
#define N_UPPER    ((1 << ROOT_LEVEL) - 1) // 1023 nodes at levels 0..9
#define MIN_DIST   1e-7f

__device__ double        g_acc;    // zero-init; reset by last block each run
__device__ unsigned int  g_count;

__device__ __forceinline__ float sq4(float4 d) {
    return d.x * d.x + d.y * d.y + d.z * d.z + d.w * d.w;
}

__global__ void __launch_bounds__(128, 8)
tm_fused_kernel(const float* __restrict__ x,
                const float* __restrict__ deltas,
                const float* __restrict__ heights,
                float* __restrict__ out) {
    __shared__ float  pd[LPB * 128];   // deferred per-leaf dot partials (8 KB)
    __shared__ double sacc[4];

    const int tid = threadIdx.x;       // owns float4 slice [tid*4, tid*4+4)
    const int bi  = blockIdx.x;        // subtree index (level-10 node = bi + 1023)
    float facc0 = 0.f, facc1 = 0.f;

    // Upper-node duty: block bi (< 1023) owns node bi (levels 0..9), L2-hot.
    if (bi < N_UPPER) {
        float4 d = ((const float4*)(deltas + (size_t)bi * DIM))[tid];
        float s = sq4(d);
        if (bi == 0) facc0 += s;
        else facc0 += __fdividef(s, fmaxf(heights[bi] - heights[(bi - 1) >> 1], MIN_DIST));
    }

    // Common path levels 0..10 summed once (independent loads, L2-hot).
    float4 wc = make_float4(0.f, 0.f, 0.f, 0.f);
    #pragma unroll
    for (int l = 0; l <= ROOT_LEVEL; l++) {
        int node = (bi >> (ROOT_LEVEL - l)) + ((1 << l) - 1);
        float4 d = ((const float4*)(deltas + (size_t)node * DIM))[tid];
        wc.x += d.x; wc.y += d.y; wc.z += d.z; wc.w += d.w;
        if (l == ROOT_LEVEL) {  // level-10 node uniquely owned by this block
            facc1 += __fdividef(sq4(d),
                fmaxf(heights[node] - heights[(node - 1) >> 1], MIN_DIST));
        }
    }

    // Leaf phase: 2 halves (level-11) x 2 quads (level-12) x 2 pairs (level-13)
    // x 2 leaves. Every row loaded exactly once; all loads independent.
    #pragma unroll
    for (int h = 0; h < 2; h++) {
        const int i_h  = bi * LPB + h * 8;
        const int n_11 = (i_h >> 3) + (N_LEAVES / 8 - 1);
        float4 d11 = ((const float4*)(deltas + (size_t)n_11 * DIM))[tid];
        facc0 += __fdividef(sq4(d11),
            fmaxf(heights[n_11] - heights[(n_11 - 1) >> 1], MIN_DIST));
        const float whx = wc.x + d11.x, why = wc.y + d11.y;
        const float whz = wc.z + d11.z, whw = wc.w + d11.w;

        #pragma unroll
        for (int q = 0; q < 2; q++) {
            const int i_q  = i_h + q * 4;
            const int n_12 = (i_q >> 2) + (N_LEAVES / 4 - 1);
            float4 da = ((const float4*)(deltas + (size_t)n_12 * DIM))[tid];
            facc1 += __fdividef(sq4(da),
                fmaxf(heights[n_12] - heights[n_11], MIN_DIST));

            #pragma unroll
            for (int p = 0; p < 2; p++) {
                const int j    = h * 8 + q * 4 + p * 2;
                const int i    = bi * LPB + j;
                const int n_13 = (i >> 1) + (N_LEAVES / 2 - 1);
                const int n_c0 = i + (N_LEAVES - 1);
                const int n_c1 = n_c0 + 1;

                float4 db  = ((const float4*)(deltas + (size_t)n_13 * DIM))[tid];
                float4 xv0 = ((const float4*)(x      + (size_t)i       * DIM))[tid];
                float4 xv1 = ((const float4*)(x      + (size_t)(i + 1) * DIM))[tid];
                float4 dc0 = ((const float4*)(deltas + (size_t)n_c0 * DIM))[tid];
                float4 dc1 = ((const float4*)(deltas + (size_t)n_c1 * DIM))[tid];

                float bx = whx + da.x + db.x;
                float by = why + da.y + db.y;
                float bz = whz + da.z + db.z;
                float bw = whw + da.w + db.w;

                pd[j * 128 + tid] =
                    xv0.x * (bx + dc0.x) + xv0.y * (by + dc0.y) +
                    xv0.z * (bz + dc0.z) + xv0.w * (bw + dc0.w);
                pd[(j + 1) * 128 + tid] =
                    xv1.x * (bx + dc1.x) + xv1.y * (by + dc1.y) +
                    xv1.z * (bz + dc1.z) + xv1.w * (bw + dc1.w);

                float hb = heights[n_13];
                facc0 += __fdividef(sq4(dc0), fmaxf(heights[n_c0] - hb, MIN_DIST));
                facc1 += __fdividef(sq4(dc1), fmaxf(heights[n_c1] - hb, MIN_DIST));
                facc0 += __fdividef(sq4(db),  fmaxf(hb - heights[n_12], MIN_DIST));
            }
        }
    }

    // Block reduction of sq accumulator (double from here on).
    double acc = (double)(facc0 + facc1);
    #pragma unroll
    for (int off = 16; off; off >>= 1)
        acc += __shfl_down_sync(0xffffffffu, acc, off);
    int warp = tid >> 5, lane = tid & 31;
    if (lane == 0) sacc[warp] = acc;
    __syncthreads();

    // Batched dot reductions: warp w reduces leaves [4w, 4w+4).
    #pragma unroll
    for (int j = warp * 4; j < warp * 4 + 4; j++) {
        float v = pd[j * 128 + lane]      + pd[j * 128 + lane + 32]
                + pd[j * 128 + lane + 64] + pd[j * 128 + lane + 96];
        #pragma unroll
        for (int off = 16; off; off >>= 1) v += __shfl_down_sync(0xffffffffu, v, off);
        if (lane == 0) out[bi * LPB + j] = v;
    }

    // Scalar epilogue: last block writes delta_total and resets state.
    if (tid == 0) {
        atomicAdd(&g_acc, sacc[0] + sacc[1] + sacc[2] + sacc[3]);
        __threadfence();
        unsigned int prev = atomicAdd(&g_count, 1u);
        if (prev == (unsigned int)(gridDim.x - 1)) {
            out[N_LEAVES] = (float)(*(volatile double*)&g_acc);
            g_acc   = 0.0;   // graph-replay safe
            g_count = 0u;
        }
    }
}

extern "C" void kernel_launch(void* const* d_in, const int* in_sizes, int n_in,
                              void* d_out, int out_size) {
    const float* x       = (const float*)d_in[0];
    const float* deltas  = (const float*)d_in[1];
    const float* heights = (const float*)d_in[2];
    float* out = (float*)d_out;

    tm_fused_kernel<<<NBLOCKS, 128>>>(x, deltas, heights, out);
}